// round 5
// baseline (speedup 1.0000x reference)
#include <cuda_runtime.h>
#include <cstdint>
#include <cstddef>

// ---------------- tile config ----------------
#define M_TILE 128
#define N_OUT  256
#define K_DIM  512
#define KC     16                  // K per pipeline stage
#define NCHUNK (K_DIM / KC)        // 32
#define STAGES 4
#define AST    20                  // padded fp32 stride (16 data + 4 pad) -> conflict-free frags
#define NTHREADS 512

// smem float offsets
#define OFF_BIAS 0
#define OFF_PT   256               // [4][128] per-n-warp partial t
#define OFF_PZZ  768               // [4][128] per-n-warp partial zz
#define OFF_AB   1280              // [2][128] alpha, beta
#define OFF_STG  2048              // stages
#define STG_FLTS (M_TILE * AST + N_OUT * AST)   // 2560 + 5120 = 7680
#define SMEM_FLTS (OFF_STG + STAGES * STG_FLTS) // 32768
#define SMEM_BYTES (SMEM_FLTS * 4)              // 131072

__device__ __forceinline__ uint32_t s2u(const void* p) {
    uint32_t a;
    asm("{ .reg .u64 t; cvta.to.shared.u64 t, %1; cvt.u32.u64 %0, t; }" : "=r"(a) : "l"(p));
    return a;
}
__device__ __forceinline__ void cp16(uint32_t dst, const float* src) {
    asm volatile("cp.async.cg.shared.global [%0], [%1], 16;" :: "r"(dst), "l"(src) : "memory");
}
__device__ __forceinline__ uint32_t f2tf32(float x) {
    uint32_t r;
    asm("cvt.rna.tf32.f32 %0, %1;" : "=r"(r) : "f"(x));
    return r;
}
__device__ __forceinline__ void mma_tf32(float* c, const uint32_t a[4], const uint32_t b[2]) {
    asm volatile(
        "mma.sync.aligned.m16n8k8.row.col.f32.tf32.tf32.f32 "
        "{%0,%1,%2,%3}, {%4,%5,%6,%7}, {%8,%9}, {%0,%1,%2,%3};"
        : "+f"(c[0]), "+f"(c[1]), "+f"(c[2]), "+f"(c[3])
        : "r"(a[0]), "r"(a[1]), "r"(a[2]), "r"(a[3]), "r"(b[0]), "r"(b[1]));
}

__global__ void __launch_bounds__(NTHREADS, 1)
fused_gemm_proj_kernel(const float* __restrict__ x,
                       const float* __restrict__ Wm,
                       const float* __restrict__ bvec,
                       float* __restrict__ out) {
    extern __shared__ __align__(128) float sm[];
    const uint32_t sb = s2u(sm);
    const int tid  = threadIdx.x;
    const int wid  = tid >> 5;
    const int lane = tid & 31;
    const int g    = lane >> 2;      // 0..7
    const int tg   = lane & 3;       // 0..3
    const int wr   = wid & 3;        // warp m index (4): 32-row slices
    const int wc   = wid >> 2;       // warp n index (4): 64-col slices
    const int rm   = wr * 32;        // warp row base (local)
    const int cn   = wc * 64;        // warp col base
    const int m0   = blockIdx.x * M_TILE;

    if (tid < 256) sm[OFF_BIAS + tid] = bvec[tid];

    // ---- cp.async stage issue (512 threads: A 512 chunks, W 1024 chunks of 16B) ----
    auto issue = [&](int k, int s) {
        const int k0 = k * KC;
        const uint32_t as = sb + (OFF_STG + s * STG_FLTS) * 4;
        const uint32_t bs = as + M_TILE * AST * 4;
        {                                              // A: 128 x 16 fp32
            const int r = tid >> 2, c = (tid & 3) * 4;
            cp16(as + (r * AST + c) * 4, x + (size_t)(m0 + r) * K_DIM + k0 + c);
        }
        #pragma unroll
        for (int i = 0; i < 2; i++) {                  // W: 256 x 16 fp32
            const int ch = tid + NTHREADS * i;
            const int n = ch >> 2, c = (ch & 3) * 4;
            cp16(bs + (n * AST + c) * 4, Wm + (size_t)n * K_DIM + k0 + c);
        }
    };

    float acc[2][8][4];
    #pragma unroll
    for (int mt = 0; mt < 2; mt++)
        #pragma unroll
        for (int nt = 0; nt < 8; nt++)
            #pragma unroll
            for (int c = 0; c < 4; c++) acc[mt][nt][c] = 0.f;

    // prologue: fill STAGES-1 stages
    #pragma unroll
    for (int s = 0; s < STAGES - 1; s++) {
        issue(s, s);
        asm volatile("cp.async.commit_group;" ::: "memory");
    }

    for (int k = 0; k < NCHUNK; k++) {
        asm volatile("cp.async.wait_group %0;" :: "n"(STAGES - 2) : "memory");
        __syncthreads();
        if (k + STAGES - 1 < NCHUNK) issue(k + STAGES - 1, (k + STAGES - 1) & (STAGES - 1));
        asm volatile("cp.async.commit_group;" ::: "memory");

        const float* As = sm + OFF_STG + (k & (STAGES - 1)) * STG_FLTS;
        const float* Bs = As + M_TILE * AST;
        #pragma unroll
        for (int ks = 0; ks < KC; ks += 8) {
            uint32_t bf[8][2];
            #pragma unroll
            for (int nt = 0; nt < 8; nt++) {
                bf[nt][0] = f2tf32(Bs[(cn + nt * 8 + g) * AST + ks + tg]);
                bf[nt][1] = f2tf32(Bs[(cn + nt * 8 + g) * AST + ks + tg + 4]);
            }
            #pragma unroll
            for (int mt = 0; mt < 2; mt++) {
                uint32_t af[4];
                const int r0 = (rm + mt * 16 + g) * AST + ks + tg;
                af[0] = f2tf32(As[r0]);
                af[1] = f2tf32(As[r0 + 8 * AST]);
                af[2] = f2tf32(As[r0 + 4]);
                af[3] = f2tf32(As[r0 + 8 * AST + 4]);
                #pragma unroll
                for (int nt = 0; nt < 8; nt++)
                    mma_tf32(acc[mt][nt], af, bf[nt]);
            }
        }
    }

    // ---------------- fused projection epilogue ----------------
    // bias for this thread's 16 columns
    float bb[8][2];
    #pragma unroll
    for (int nt = 0; nt < 8; nt++) {
        bb[nt][0] = sm[OFF_BIAS + cn + nt * 8 + tg * 2];
        bb[nt][1] = sm[OFF_BIAS + cn + nt * 8 + tg * 2 + 1];
    }

    // pass 1: per-row partials over this warp's 64 columns
    #pragma unroll
    for (int mt = 0; mt < 2; mt++) {
        #pragma unroll
        for (int h = 0; h < 2; h++) {
            float t = 0.f, zz = 0.f;
            #pragma unroll
            for (int nt = 0; nt < 8; nt++) {
                const float z0 = acc[mt][nt][h * 2]     - bb[nt][0];
                const float z1 = acc[mt][nt][h * 2 + 1] - bb[nt][1];
                t += z0 + z1;
                zz = fmaf(z0, z0, zz);
                zz = fmaf(z1, z1, zz);
            }
            #pragma unroll
            for (int o = 1; o <= 2; o <<= 1) {          // reduce over tg (4 lanes)
                t  += __shfl_xor_sync(0xffffffffu, t,  o);
                zz += __shfl_xor_sync(0xffffffffu, zz, o);
            }
            if (tg == 0) {
                const int rloc = rm + mt * 16 + g + h * 8;
                sm[OFF_PT  + wc * 128 + rloc] = t;
                sm[OFF_PZZ + wc * 128 + rloc] = zz;
            }
        }
    }
    __syncthreads();

    if (tid < 128) {
        const float t  = sm[OFF_PT + tid] + sm[OFF_PT + 128 + tid] +
                         sm[OFF_PT + 256 + tid] + sm[OFF_PT + 384 + tid];
        const float zz = sm[OFF_PZZ + tid] + sm[OFF_PZZ + 128 + tid] +
                         sm[OFF_PZZ + 256 + tid] + sm[OFF_PZZ + 384 + tid];
        const float S = 0.1f, R2 = 0.02f, invN = 1.0f / 256.0f;
        const float tc = fminf(fmaxf(t, -S), S);
        const float d1 = (tc - t) * invN;
        const float s1 = fmaf(fmaf(256.f, d1, 2.f * t), d1, zz);
        const bool ok1 = s1 <= R2;
        const float znorm = sqrtf(fmaxf(zz, 1e-12f));
        const float scale = fminf(1.f, 0.141421356237309515f / znorm);
        const bool ok2 = fabsf(t) * scale <= S;
        const float denom = fmaxf(fmaf(256.f, zz, -t * t), 1e-12f);
        const float c3 = sqrtf((256.f * R2 - S * S) / denom);
        const float sp = (t > 0.f) ? S : ((t < 0.f) ? -S : 0.f);
        const float b3 = fmaf(-c3, t, sp) * invN;
        sm[OFF_AB + tid]       = ok1 ? 1.f : (ok2 ? scale : c3);   // alpha
        sm[OFF_AB + 128 + tid] = ok1 ? d1  : (ok2 ? 0.f   : b3);   // beta
    }
    __syncthreads();

    // pass 2: y = alpha*z + beta, float2 stores
    #pragma unroll
    for (int mt = 0; mt < 2; mt++) {
        #pragma unroll
        for (int h = 0; h < 2; h++) {
            const int rloc  = rm + mt * 16 + g + h * 8;
            const float al  = sm[OFF_AB + rloc];
            const float be  = sm[OFF_AB + 128 + rloc];
            float* op = out + (size_t)(m0 + rloc) * N_OUT + cn + tg * 2;
            #pragma unroll
            for (int nt = 0; nt < 8; nt++) {
                float2 v;
                v.x = fmaf(al, acc[mt][nt][h * 2]     - bb[nt][0], be);
                v.y = fmaf(al, acc[mt][nt][h * 2 + 1] - bb[nt][1], be);
                *reinterpret_cast<float2*>(op + nt * 8) = v;
            }
        }
    }
}

extern "C" void kernel_launch(void* const* d_in, const int* in_sizes, int n_in,
                              void* d_out, int out_size) {
    const float* x = (const float*)d_in[0];   // [B, 512]
    const float* W = (const float*)d_in[1];   // [256, 512]
    const float* b = (const float*)d_in[2];   // [256]
    float* out = (float*)d_out;               // [B, 256]
    const int Brows = in_sizes[0] / K_DIM;

    static bool attr_set = false;
    if (!attr_set) {
        cudaFuncSetAttribute(fused_gemm_proj_kernel,
                             cudaFuncAttributeMaxDynamicSharedMemorySize, SMEM_BYTES);
        attr_set = true;
    }
    fused_gemm_proj_kernel<<<Brows / M_TILE, NTHREADS, SMEM_BYTES>>>(x, W, b, out);
}

// round 6
// speedup vs baseline: 1.0570x; 1.0570x over previous
#include <cuda_runtime.h>
#include <cstdint>
#include <cstddef>

// ---------------- tile config ----------------
#define M_TILE 128
#define N_OUT  256
#define K_DIM  512
#define KC     16                  // K per pipeline stage
#define NCHUNK (K_DIM / KC)        // 32
#define STAGES 4
#define AST    20                  // padded fp32 stride (16 data + 4 pad) -> conflict-free frags
#define NTHREADS 256

// smem float offsets
#define OFF_BIAS 0
#define OFF_PT   256               // [4][128] per-n-warp partial t
#define OFF_PZZ  768               // [4][128] per-n-warp partial zz
#define OFF_AB   1280              // [2][128] alpha, beta
#define OFF_STG  2048              // stages
#define STG_FLTS (M_TILE * AST + N_OUT * AST)   // 2560 + 5120 = 7680
#define SMEM_FLTS (OFF_STG + STAGES * STG_FLTS) // 32768
#define SMEM_BYTES (SMEM_FLTS * 4)              // 131072

__device__ __forceinline__ uint32_t s2u(const void* p) {
    uint32_t a;
    asm("{ .reg .u64 t; cvta.to.shared.u64 t, %1; cvt.u32.u64 %0, t; }" : "=r"(a) : "l"(p));
    return a;
}
__device__ __forceinline__ void cp16(uint32_t dst, const float* src) {
    asm volatile("cp.async.cg.shared.global [%0], [%1], 16;" :: "r"(dst), "l"(src) : "memory");
}
__device__ __forceinline__ uint32_t f2tf32(float x) {
    uint32_t r;
    asm("cvt.rna.tf32.f32 %0, %1;" : "=r"(r) : "f"(x));
    return r;
}
__device__ __forceinline__ void mma_tf32(float* c, const uint32_t a[4], const uint32_t b[2]) {
    asm volatile(
        "mma.sync.aligned.m16n8k8.row.col.f32.tf32.tf32.f32 "
        "{%0,%1,%2,%3}, {%4,%5,%6,%7}, {%8,%9}, {%0,%1,%2,%3};"
        : "+f"(c[0]), "+f"(c[1]), "+f"(c[2]), "+f"(c[3])
        : "r"(a[0]), "r"(a[1]), "r"(a[2]), "r"(a[3]), "r"(b[0]), "r"(b[1]));
}

__global__ void __launch_bounds__(NTHREADS, 1)
fused_gemm_proj_kernel(const float* __restrict__ x,
                       const float* __restrict__ Wm,
                       const float* __restrict__ bvec,
                       float* __restrict__ out) {
    extern __shared__ __align__(128) float sm[];
    const uint32_t sb = s2u(sm);
    const int tid  = threadIdx.x;
    const int wid  = tid >> 5;
    const int lane = tid & 31;
    const int g    = lane >> 2;      // 0..7
    const int tg   = lane & 3;       // 0..3
    const int wr   = wid & 1;        // warp m index (2): 64-row slices
    const int wc   = wid >> 1;       // warp n index (4): 64-col slices
    const int rm   = wr * 64;        // warp row base (local)
    const int cn   = wc * 64;        // warp col base
    const int m0   = blockIdx.x * M_TILE;

    sm[OFF_BIAS + tid] = bvec[tid];

    // ---- cp.async stage issue (256 threads) ----
    auto issue = [&](int k, int s) {
        const int k0 = k * KC;
        const uint32_t as = sb + (OFF_STG + s * STG_FLTS) * 4;
        const uint32_t bs = as + M_TILE * AST * 4;
        #pragma unroll
        for (int i = 0; i < 2; i++) {                  // A: 512 x 16B chunks
            const int ch = tid + NTHREADS * i;
            const int r = ch >> 2, c = (ch & 3) * 4;
            cp16(as + (r * AST + c) * 4, x + (size_t)(m0 + r) * K_DIM + k0 + c);
        }
        #pragma unroll
        for (int i = 0; i < 4; i++) {                  // W: 1024 x 16B chunks
            const int ch = tid + NTHREADS * i;
            const int n = ch >> 2, c = (ch & 3) * 4;
            cp16(bs + (n * AST + c) * 4, Wm + (size_t)n * K_DIM + k0 + c);
        }
    };

    float acc[4][8][4];
    #pragma unroll
    for (int mt = 0; mt < 4; mt++)
        #pragma unroll
        for (int nt = 0; nt < 8; nt++)
            #pragma unroll
            for (int c = 0; c < 4; c++) acc[mt][nt][c] = 0.f;

    // prologue: fill STAGES-1 stages
    #pragma unroll
    for (int s = 0; s < STAGES - 1; s++) {
        issue(s, s);
        asm volatile("cp.async.commit_group;" ::: "memory");
    }

    // per-thread constant fragment offsets (folded into LDS immediates)
    const int aoff = (rm + g) * AST + tg;   // + mt*16*AST (+8*AST) (+4) + ks
    const int boff = (cn + g) * AST + tg;   // + nt*8*AST (+4) + ks

    for (int k = 0; k < NCHUNK; k++) {
        asm volatile("cp.async.wait_group %0;" :: "n"(STAGES - 2) : "memory");
        __syncthreads();
        if (k + STAGES - 1 < NCHUNK) issue(k + STAGES - 1, (k + STAGES - 1) & (STAGES - 1));
        asm volatile("cp.async.commit_group;" ::: "memory");

        const float* As = sm + OFF_STG + (k & (STAGES - 1)) * STG_FLTS;
        const float* Bs = As + M_TILE * AST;
        const float* ap = As + aoff;
        const float* bp = Bs + boff;

        // prefetch raw fragments for ks = 0
        float pB[8][2], pA[4][4];
        #pragma unroll
        for (int nt = 0; nt < 8; nt++) {
            pB[nt][0] = bp[nt * 8 * AST];
            pB[nt][1] = bp[nt * 8 * AST + 4];
        }
        #pragma unroll
        for (int mt = 0; mt < 4; mt++) {
            pA[mt][0] = ap[mt * 16 * AST];
            pA[mt][1] = ap[(mt * 16 + 8) * AST];
            pA[mt][2] = ap[mt * 16 * AST + 4];
            pA[mt][3] = ap[(mt * 16 + 8) * AST + 4];
        }

        #pragma unroll
        for (int ks = 0; ks < KC; ks += 8) {
            // convert current fragments out of the prefetch registers
            uint32_t bf[8][2], af[4][4];
            #pragma unroll
            for (int nt = 0; nt < 8; nt++) {
                bf[nt][0] = f2tf32(pB[nt][0]);
                bf[nt][1] = f2tf32(pB[nt][1]);
            }
            #pragma unroll
            for (int mt = 0; mt < 4; mt++) {
                af[mt][0] = f2tf32(pA[mt][0]);
                af[mt][1] = f2tf32(pA[mt][1]);
                af[mt][2] = f2tf32(pA[mt][2]);
                af[mt][3] = f2tf32(pA[mt][3]);
            }
            // prefetch raw fragments for ks = 8 while ks = 0 MMAs run
            if (ks == 0) {
                #pragma unroll
                for (int nt = 0; nt < 8; nt++) {
                    pB[nt][0] = bp[nt * 8 * AST + 8];
                    pB[nt][1] = bp[nt * 8 * AST + 12];
                }
                #pragma unroll
                for (int mt = 0; mt < 4; mt++) {
                    pA[mt][0] = ap[mt * 16 * AST + 8];
                    pA[mt][1] = ap[(mt * 16 + 8) * AST + 8];
                    pA[mt][2] = ap[mt * 16 * AST + 12];
                    pA[mt][3] = ap[(mt * 16 + 8) * AST + 12];
                }
            }
            #pragma unroll
            for (int mt = 0; mt < 4; mt++)
                #pragma unroll
                for (int nt = 0; nt < 8; nt++)
                    mma_tf32(acc[mt][nt], af[mt], bf[nt]);
        }
    }

    // ---------------- fused projection epilogue ----------------
    float bb[8][2];
    #pragma unroll
    for (int nt = 0; nt < 8; nt++) {
        bb[nt][0] = sm[OFF_BIAS + cn + nt * 8 + tg * 2];
        bb[nt][1] = sm[OFF_BIAS + cn + nt * 8 + tg * 2 + 1];
    }

    // pass 1: per-row partials over this warp's 64 columns
    #pragma unroll
    for (int mt = 0; mt < 4; mt++) {
        #pragma unroll
        for (int h = 0; h < 2; h++) {
            float t = 0.f, zz = 0.f;
            #pragma unroll
            for (int nt = 0; nt < 8; nt++) {
                const float z0 = acc[mt][nt][h * 2]     - bb[nt][0];
                const float z1 = acc[mt][nt][h * 2 + 1] - bb[nt][1];
                t += z0 + z1;
                zz = fmaf(z0, z0, zz);
                zz = fmaf(z1, z1, zz);
            }
            #pragma unroll
            for (int o = 1; o <= 2; o <<= 1) {          // reduce over tg (4 lanes)
                t  += __shfl_xor_sync(0xffffffffu, t,  o);
                zz += __shfl_xor_sync(0xffffffffu, zz, o);
            }
            if (tg == 0) {
                const int rloc = rm + mt * 16 + g + h * 8;
                sm[OFF_PT  + wc * 128 + rloc] = t;
                sm[OFF_PZZ + wc * 128 + rloc] = zz;
            }
        }
    }
    __syncthreads();

    if (tid < 128) {
        const float t  = sm[OFF_PT + tid] + sm[OFF_PT + 128 + tid] +
                         sm[OFF_PT + 256 + tid] + sm[OFF_PT + 384 + tid];
        const float zz = sm[OFF_PZZ + tid] + sm[OFF_PZZ + 128 + tid] +
                         sm[OFF_PZZ + 256 + tid] + sm[OFF_PZZ + 384 + tid];
        const float S = 0.1f, R2 = 0.02f, invN = 1.0f / 256.0f;
        const float tc = fminf(fmaxf(t, -S), S);
        const float d1 = (tc - t) * invN;
        const float s1 = fmaf(fmaf(256.f, d1, 2.f * t), d1, zz);
        const bool ok1 = s1 <= R2;
        const float znorm = sqrtf(fmaxf(zz, 1e-12f));
        const float scale = fminf(1.f, 0.141421356237309515f / znorm);
        const bool ok2 = fabsf(t) * scale <= S;
        const float denom = fmaxf(fmaf(256.f, zz, -t * t), 1e-12f);
        const float c3 = sqrtf((256.f * R2 - S * S) / denom);
        const float sp = (t > 0.f) ? S : ((t < 0.f) ? -S : 0.f);
        const float b3 = fmaf(-c3, t, sp) * invN;
        sm[OFF_AB + tid]       = ok1 ? 1.f : (ok2 ? scale : c3);   // alpha
        sm[OFF_AB + 128 + tid] = ok1 ? d1  : (ok2 ? 0.f   : b3);   // beta
    }
    __syncthreads();

    // pass 2: y = alpha*z + beta, float2 stores
    #pragma unroll
    for (int mt = 0; mt < 4; mt++) {
        #pragma unroll
        for (int h = 0; h < 2; h++) {
            const int rloc  = rm + mt * 16 + g + h * 8;
            const float al  = sm[OFF_AB + rloc];
            const float be  = sm[OFF_AB + 128 + rloc];
            float* op = out + (size_t)(m0 + rloc) * N_OUT + cn + tg * 2;
            #pragma unroll
            for (int nt = 0; nt < 8; nt++) {
                float2 v;
                v.x = fmaf(al, acc[mt][nt][h * 2]     - bb[nt][0], be);
                v.y = fmaf(al, acc[mt][nt][h * 2 + 1] - bb[nt][1], be);
                *reinterpret_cast<float2*>(op + nt * 8) = v;
            }
        }
    }
}

extern "C" void kernel_launch(void* const* d_in, const int* in_sizes, int n_in,
                              void* d_out, int out_size) {
    const float* x = (const float*)d_in[0];   // [B, 512]
    const float* W = (const float*)d_in[1];   // [256, 512]
    const float* b = (const float*)d_in[2];   // [256]
    float* out = (float*)d_out;               // [B, 256]
    const int Brows = in_sizes[0] / K_DIM;

    static bool attr_set = false;
    if (!attr_set) {
        cudaFuncSetAttribute(fused_gemm_proj_kernel,
                             cudaFuncAttributeMaxDynamicSharedMemorySize, SMEM_BYTES);
        attr_set = true;
    }
    fused_gemm_proj_kernel<<<Brows / M_TILE, NTHREADS, SMEM_BYTES>>>(x, W, b, out);
}

// round 7
// speedup vs baseline: 1.0702x; 1.0125x over previous
#include <cuda_runtime.h>
#include <cstdint>
#include <cstddef>

// ---------------- tile config ----------------
#define M_TILE 64
#define N_OUT  256
#define K_DIM  512
#define KC     16                  // K per pipeline stage
#define NCHUNK (K_DIM / KC)        // 32
#define STAGES 4
#define AST    20                  // padded fp32 stride (16 data + 4 pad) -> conflict-free frags
#define NTHREADS 256

// smem float offsets
#define OFF_BIAS 0                 // 256 floats
#define OFF_PT   256               // [4][64] per-n-warp partial t
#define OFF_PZZ  512               // [4][64] partial zz
#define OFF_AB   768               // [2][64] alpha, beta
#define OFF_STG  1024              // stages (4KB-aligned)
#define STG_FLTS (M_TILE * AST + N_OUT * AST)   // 1280 + 5120 = 6400
#define SMEM_FLTS (OFF_STG + STAGES * STG_FLTS) // 26624
#define SMEM_BYTES (SMEM_FLTS * 4)              // 106496  -> 2 CTAs/SM

__device__ __forceinline__ uint32_t s2u(const void* p) {
    uint32_t a;
    asm("{ .reg .u64 t; cvta.to.shared.u64 t, %1; cvt.u32.u64 %0, t; }" : "=r"(a) : "l"(p));
    return a;
}
__device__ __forceinline__ void cp16(uint32_t dst, const float* src) {
    asm volatile("cp.async.cg.shared.global [%0], [%1], 16;" :: "r"(dst), "l"(src) : "memory");
}
__device__ __forceinline__ uint32_t f2tf32(float x) {
    uint32_t r;
    asm("cvt.rna.tf32.f32 %0, %1;" : "=r"(r) : "f"(x));
    return r;
}
__device__ __forceinline__ void mma_tf32(float* c, const uint32_t a[4], const uint32_t b[2]) {
    asm volatile(
        "mma.sync.aligned.m16n8k8.row.col.f32.tf32.tf32.f32 "
        "{%0,%1,%2,%3}, {%4,%5,%6,%7}, {%8,%9}, {%0,%1,%2,%3};"
        : "+f"(c[0]), "+f"(c[1]), "+f"(c[2]), "+f"(c[3])
        : "r"(a[0]), "r"(a[1]), "r"(a[2]), "r"(a[3]), "r"(b[0]), "r"(b[1]));
}

__global__ void __launch_bounds__(NTHREADS, 2)
fused_gemm_proj_kernel(const float* __restrict__ x,
                       const float* __restrict__ Wm,
                       const float* __restrict__ bvec,
                       float* __restrict__ out) {
    extern __shared__ __align__(128) float sm[];
    const uint32_t sb = s2u(sm);
    const int tid  = threadIdx.x;
    const int wid  = tid >> 5;
    const int lane = tid & 31;
    const int g    = lane >> 2;      // 0..7
    const int tg   = lane & 3;       // 0..3
    const int wr   = wid & 1;        // warp m index (2): 32-row slices
    const int wc   = wid >> 1;       // warp n index (4): 64-col slices
    const int rm   = wr * 32;        // warp row base (local)
    const int cn   = wc * 64;        // warp col base
    const int m0   = blockIdx.x * M_TILE;

    sm[OFF_BIAS + tid] = bvec[tid];

    // ---- cp.async stage issue (256 threads, 5 x 16B each) ----
    auto issue = [&](int k, int s) {
        const int k0 = k * KC;
        const uint32_t as = sb + (OFF_STG + s * STG_FLTS) * 4;
        const uint32_t bs = as + M_TILE * AST * 4;
        {                                              // A: 256 x 16B chunks
            const int r = tid >> 2, c = (tid & 3) * 4;
            cp16(as + (r * AST + c) * 4, x + (size_t)(m0 + r) * K_DIM + k0 + c);
        }
        #pragma unroll
        for (int i = 0; i < 4; i++) {                  // W: 1024 x 16B chunks
            const int ch = tid + NTHREADS * i;
            const int n = ch >> 2, c = (ch & 3) * 4;
            cp16(bs + (n * AST + c) * 4, Wm + (size_t)n * K_DIM + k0 + c);
        }
    };

    float acc[2][8][4];
    #pragma unroll
    for (int mt = 0; mt < 2; mt++)
        #pragma unroll
        for (int nt = 0; nt < 8; nt++)
            #pragma unroll
            for (int c = 0; c < 4; c++) acc[mt][nt][c] = 0.f;

    // prologue: fill STAGES-1 stages
    #pragma unroll
    for (int s = 0; s < STAGES - 1; s++) {
        issue(s, s);
        asm volatile("cp.async.commit_group;" ::: "memory");
    }

    const int aoff = (rm + g) * AST + tg;
    const int boff = (cn + g) * AST + tg;

    for (int k = 0; k < NCHUNK; k++) {
        asm volatile("cp.async.wait_group %0;" :: "n"(STAGES - 2) : "memory");
        __syncthreads();
        if (k + STAGES - 1 < NCHUNK) issue(k + STAGES - 1, (k + STAGES - 1) & (STAGES - 1));
        asm volatile("cp.async.commit_group;" ::: "memory");

        const float* As = sm + OFF_STG + (k & (STAGES - 1)) * STG_FLTS;
        const float* ap = As + aoff;
        const float* bp = As + M_TILE * AST + boff;

        #pragma unroll
        for (int ks = 0; ks < KC; ks += 8) {
            uint32_t bf[8][2];
            #pragma unroll
            for (int nt = 0; nt < 8; nt++) {
                bf[nt][0] = f2tf32(bp[nt * 8 * AST + ks]);
                bf[nt][1] = f2tf32(bp[nt * 8 * AST + ks + 4]);
            }
            #pragma unroll
            for (int mt = 0; mt < 2; mt++) {
                uint32_t af[4];
                af[0] = f2tf32(ap[mt * 16 * AST + ks]);
                af[1] = f2tf32(ap[(mt * 16 + 8) * AST + ks]);
                af[2] = f2tf32(ap[mt * 16 * AST + ks + 4]);
                af[3] = f2tf32(ap[(mt * 16 + 8) * AST + ks + 4]);
                #pragma unroll
                for (int nt = 0; nt < 8; nt++)
                    mma_tf32(acc[mt][nt], af, bf[nt]);
            }
        }
    }

    // ---------------- fused projection epilogue ----------------
    float bb[8][2];
    #pragma unroll
    for (int nt = 0; nt < 8; nt++) {
        bb[nt][0] = sm[OFF_BIAS + cn + nt * 8 + tg * 2];
        bb[nt][1] = sm[OFF_BIAS + cn + nt * 8 + tg * 2 + 1];
    }

    // pass 1: per-row partials over this warp's 64 columns
    #pragma unroll
    for (int mt = 0; mt < 2; mt++) {
        #pragma unroll
        for (int h = 0; h < 2; h++) {
            float t = 0.f, zz = 0.f;
            #pragma unroll
            for (int nt = 0; nt < 8; nt++) {
                const float z0 = acc[mt][nt][h * 2]     - bb[nt][0];
                const float z1 = acc[mt][nt][h * 2 + 1] - bb[nt][1];
                t += z0 + z1;
                zz = fmaf(z0, z0, zz);
                zz = fmaf(z1, z1, zz);
            }
            #pragma unroll
            for (int o = 1; o <= 2; o <<= 1) {          // reduce over tg (4 lanes)
                t  += __shfl_xor_sync(0xffffffffu, t,  o);
                zz += __shfl_xor_sync(0xffffffffu, zz, o);
            }
            if (tg == 0) {
                const int rloc = rm + mt * 16 + g + h * 8;
                sm[OFF_PT  + wc * 64 + rloc] = t;
                sm[OFF_PZZ + wc * 64 + rloc] = zz;
            }
        }
    }
    __syncthreads();

    if (tid < 64) {
        const float t  = sm[OFF_PT + tid] + sm[OFF_PT + 64 + tid] +
                         sm[OFF_PT + 128 + tid] + sm[OFF_PT + 192 + tid];
        const float zz = sm[OFF_PZZ + tid] + sm[OFF_PZZ + 64 + tid] +
                         sm[OFF_PZZ + 128 + tid] + sm[OFF_PZZ + 192 + tid];
        const float S = 0.1f, R2 = 0.02f, invN = 1.0f / 256.0f;
        const float tc = fminf(fmaxf(t, -S), S);
        const float d1 = (tc - t) * invN;
        const float s1 = fmaf(fmaf(256.f, d1, 2.f * t), d1, zz);
        const bool ok1 = s1 <= R2;
        const float znorm = sqrtf(fmaxf(zz, 1e-12f));
        const float scale = fminf(1.f, 0.141421356237309515f / znorm);
        const bool ok2 = fabsf(t) * scale <= S;
        const float denom = fmaxf(fmaf(256.f, zz, -t * t), 1e-12f);
        const float c3 = sqrtf((256.f * R2 - S * S) / denom);
        const float sp = (t > 0.f) ? S : ((t < 0.f) ? -S : 0.f);
        const float b3 = fmaf(-c3, t, sp) * invN;
        sm[OFF_AB + tid]      = ok1 ? 1.f : (ok2 ? scale : c3);   // alpha
        sm[OFF_AB + 64 + tid] = ok1 ? d1  : (ok2 ? 0.f   : b3);   // beta
    }
    __syncthreads();

    // pass 2: y = alpha*z + beta, float2 stores
    #pragma unroll
    for (int mt = 0; mt < 2; mt++) {
        #pragma unroll
        for (int h = 0; h < 2; h++) {
            const int rloc  = rm + mt * 16 + g + h * 8;
            const float al  = sm[OFF_AB + rloc];
            const float be  = sm[OFF_AB + 64 + rloc];
            float* op = out + (size_t)(m0 + rloc) * N_OUT + cn + tg * 2;
            #pragma unroll
            for (int nt = 0; nt < 8; nt++) {
                float2 v;
                v.x = fmaf(al, acc[mt][nt][h * 2]     - bb[nt][0], be);
                v.y = fmaf(al, acc[mt][nt][h * 2 + 1] - bb[nt][1], be);
                *reinterpret_cast<float2*>(op + nt * 8) = v;
            }
        }
    }
}

extern "C" void kernel_launch(void* const* d_in, const int* in_sizes, int n_in,
                              void* d_out, int out_size) {
    const float* x = (const float*)d_in[0];   // [B, 512]
    const float* W = (const float*)d_in[1];   // [256, 512]
    const float* b = (const float*)d_in[2];   // [256]
    float* out = (float*)d_out;               // [B, 256]
    const int Brows = in_sizes[0] / K_DIM;

    static bool attr_set = false;
    if (!attr_set) {
        cudaFuncSetAttribute(fused_gemm_proj_kernel,
                             cudaFuncAttributeMaxDynamicSharedMemorySize, SMEM_BYTES);
        attr_set = true;
    }
    fused_gemm_proj_kernel<<<Brows / M_TILE, NTHREADS, SMEM_BYTES>>>(x, W, b, out);
}